// round 1
// baseline (speedup 1.0000x reference)
#include <cuda_runtime.h>

// Adaptive avg pool (32,50,50,768) NHWC -> (32,7,7,768), fp32.
// Static geometry: all H/W windows are [7*o, 7*o+8) (size 8, stride 7).
// Fused single kernel: one CTA per (batch, oh). 4 h-groups x 192 channel-vec
// lanes; register accumulation over the 7 ow windows; shared-memory tree
// reduction across h-groups.

#define NB   32
#define HIN  50
#define WIN  50
#define CH   768
#define CV   192   // CH / 4 (float4 lanes)
#define HO   7
#define WO   7

static __device__ __forceinline__ void f4add(float4& a, const float4& v) {
    a.x += v.x; a.y += v.y; a.z += v.z; a.w += v.w;
}

__global__ __launch_bounds__(768, 1)
void adaptive_pool_kernel(const float4* __restrict__ in4, float4* __restrict__ out4) {
    __shared__ float4 buf[2][CV * WO];   // 2 * 192 * 7 * 16B = 43008 B

    const int bid  = blockIdx.x;         // 0..223
    const int b    = bid / HO;
    const int oh   = bid % HO;
    const int tid  = threadIdx.x;
    const int g    = tid / CV;           // h-group 0..3 (2 rows each)
    const int cvec = tid % CV;           // float4 channel lane
    const int h0   = oh * 7 + g * 2;     // window start + group offset

    float4 acc[WO];
    #pragma unroll
    for (int i = 0; i < WO; ++i) acc[i] = make_float4(0.f, 0.f, 0.f, 0.f);

    #pragma unroll
    for (int r = 0; r < 2; ++r) {
        const float4* row = in4 + ((size_t)((b * HIN) + h0 + r) * WIN) * CV + cvec;
        #pragma unroll
        for (int w = 0; w < WIN; ++w) {
            float4 v = row[(size_t)w * CV];
            int owa = w / 7; if (owa > 6) owa = 6;   // compile-time under unroll
            f4add(acc[owa], v);
            if ((w % 7 == 0) && (w > 0) && (w < 49)) {
                f4add(acc[w / 7 - 1], v);            // boundary col in two windows
            }
        }
    }

    // Tree reduction over the 4 h-groups.
    if (g >= 2) {
        float4* dst = buf[g - 2];
        #pragma unroll
        for (int i = 0; i < WO; ++i) dst[i * CV + cvec] = acc[i];
    }
    __syncthreads();
    if (g < 2) {
        const float4* src = buf[g];
        #pragma unroll
        for (int i = 0; i < WO; ++i) f4add(acc[i], src[i * CV + cvec]);
    }
    __syncthreads();
    if (g == 1) {
        #pragma unroll
        for (int i = 0; i < WO; ++i) buf[0][i * CV + cvec] = acc[i];
    }
    __syncthreads();
    if (g == 0) {
        #pragma unroll
        for (int i = 0; i < WO; ++i) f4add(acc[i], buf[0][i * CV + cvec]);

        const float s = 1.0f / 64.0f;   // 8x8 window
        float4* o = out4 + ((size_t)(b * HO + oh) * WO) * CV + cvec;
        #pragma unroll
        for (int ow = 0; ow < WO; ++ow) {
            float4 rr = acc[ow];
            rr.x *= s; rr.y *= s; rr.z *= s; rr.w *= s;
            o[(size_t)ow * CV] = rr;
        }
    }
}

extern "C" void kernel_launch(void* const* d_in, const int* in_sizes, int n_in,
                              void* d_out, int out_size) {
    const float4* in4 = (const float4*)d_in[0];
    float4* out4 = (float4*)d_out;
    adaptive_pool_kernel<<<NB * HO, 768>>>(in4, out4);
}